// round 7
// baseline (speedup 1.0000x reference)
#include <cuda_runtime.h>
#include <math.h>

#define NN   20000
#define EE   320000
#define INDIM 256
#define HID  64
#define NH   4
#define CHD  64
#define HC   256   // NH*CHD
#define DFF  128
#define NL   4

// ---------------- scratch (device globals; no allocation allowed) ----------------
__device__ float g_h  [(size_t)NN * HID];   // hidden state
__device__ float g_xh [(size_t)NN * HC];    // per-layer projected features
__device__ float g_agg[(size_t)NN * HC];    // aggregated messages
__device__ float g_f1 [(size_t)NN * DFF];   // FFN intermediate
__device__ float g_as [(size_t)NN * NH];    // attention scores (src side)
__device__ float g_ad [(size_t)NN * NH];    // attention scores (dst side)
__device__ int   g_deg[NN];
__device__ int   g_fill[NN];
__device__ int   g_rowptr[NN + 1];
__device__ int   g_col[EE];

__device__ __forceinline__ float lrelu(float x) { return x > 0.f ? x : 0.2f * x; }

// ---------------- CSR build ----------------
__global__ void zero_kernel() {
    int i = blockIdx.x * blockDim.x + threadIdx.x;
    if (i < NN) { g_deg[i] = 0; g_fill[i] = 0; }
}

__global__ void count_kernel(const int* __restrict__ ei) {
    int e = blockIdx.x * blockDim.x + threadIdx.x;
    if (e < EE) atomicAdd(&g_deg[ei[EE + e]], 1);
}

__global__ void scan_kernel() {
    __shared__ int s[1024];
    int t = threadIdx.x;
    const int CHK = (NN + 1023) / 1024;  // 20
    int base = t * CHK;
    int sum = 0;
    #pragma unroll
    for (int i = 0; i < CHK; i++) {
        int idx = base + i;
        if (idx < NN) sum += g_deg[idx];
    }
    s[t] = sum;
    __syncthreads();
    for (int off = 1; off < 1024; off <<= 1) {
        int v = (t >= off) ? s[t - off] : 0;
        __syncthreads();
        s[t] += v;
        __syncthreads();
    }
    int run = (t == 0) ? 0 : s[t - 1];
    #pragma unroll
    for (int i = 0; i < CHK; i++) {
        int idx = base + i;
        if (idx < NN) { g_rowptr[idx] = run; run += g_deg[idx]; }
    }
    if (t == 0) g_rowptr[NN] = s[1023];
}

__global__ void scatter_kernel(const int* __restrict__ ei) {
    int e = blockIdx.x * blockDim.x + threadIdx.x;
    if (e < EE) {
        int d = ei[EE + e];
        int pos = g_rowptr[d] + atomicAdd(&g_fill[d], 1);
        g_col[pos] = ei[e];  // src
    }
}

// ======================= GEMM core (double-buffered, shared by all variants) ======
// TM x 64 block tile (TM = 128 or 64), 256 threads, (TM/16) x 4 per thread, k-tile 16.
// Software-pipelined: global loads for tile t+1 issued before compute of tile t;
// one __syncthreads() per k-tile.
// acc layout: thread (tx = tid&15, ty = tid>>4) owns rows bm+ty*RM..+RM-1, cols bn+tx*4..+3
template <int K, int TM>
__device__ __forceinline__ void gemm_core(const float* __restrict__ A,
                                          const float* __restrict__ B, int NC,
                                          int bm, int bn, int M,
                                          float acc[TM / 16][4]) {
    constexpr int RM = TM / 16;
    constexpr int NT = K / 16;        // number of k-tiles
    constexpr int AR = TM / 64;       // A float4 loads per thread per tile
    __shared__ __align__(16) float As[2][16][TM + 8];  // transposed: As[buf][k][m]
    __shared__ __align__(16) float Bs[2][16][68];      // Bs[buf][k][n]
    const int tid = threadIdx.x;
    const int tx = tid & 15, ty = tid >> 4;

    #pragma unroll
    for (int i = 0; i < RM; i++)
        #pragma unroll
        for (int j = 0; j < 4; j++) acc[i][j] = 0.f;

    const int ar = tid >> 2;          // 0..63
    const int ac = (tid & 3) * 4;     // 0,4,8,12
    const int br = tid >> 4;          // 0..15
    const int bcl = (tid & 15) * 4;   // 0..60

    float4 aReg[AR];
    float4 bReg;

    // prologue: load tile 0 into buffer 0
    #pragma unroll
    for (int rr = 0; rr < AR; rr++) {
        int row = bm + ar + rr * 64;
        aReg[rr] = make_float4(0.f, 0.f, 0.f, 0.f);
        if (row < M) aReg[rr] = *(const float4*)(A + (size_t)row * K + ac);
    }
    bReg = *(const float4*)(B + (size_t)br * NC + bn + bcl);
    #pragma unroll
    for (int rr = 0; rr < AR; rr++) {
        int r = ar + rr * 64;
        As[0][ac + 0][r] = aReg[rr].x; As[0][ac + 1][r] = aReg[rr].y;
        As[0][ac + 2][r] = aReg[rr].z; As[0][ac + 3][r] = aReg[rr].w;
    }
    *(float4*)&Bs[0][br][bcl] = bReg;
    __syncthreads();

    #pragma unroll
    for (int t = 0; t < NT; t++) {
        const int cur = t & 1;
        // issue next tile's global loads before compute (latency hidden by FMAs)
        if (t + 1 < NT) {
            int k0 = (t + 1) * 16;
            #pragma unroll
            for (int rr = 0; rr < AR; rr++) {
                int row = bm + ar + rr * 64;
                aReg[rr] = make_float4(0.f, 0.f, 0.f, 0.f);
                if (row < M) aReg[rr] = *(const float4*)(A + (size_t)row * K + k0 + ac);
            }
            bReg = *(const float4*)(B + (size_t)(k0 + br) * NC + bn + bcl);
        }
        // compute on current buffer
        #pragma unroll
        for (int k = 0; k < 16; k++) {
            float a[RM];
            #pragma unroll
            for (int r4 = 0; r4 < RM / 4; r4++) {
                float4 av = *(const float4*)&As[cur][k][ty * RM + r4 * 4];
                a[r4 * 4 + 0] = av.x; a[r4 * 4 + 1] = av.y;
                a[r4 * 4 + 2] = av.z; a[r4 * 4 + 3] = av.w;
            }
            float4 bv = *(const float4*)&Bs[cur][k][tx * 4];
            float b[4] = {bv.x, bv.y, bv.z, bv.w};
            #pragma unroll
            for (int i = 0; i < RM; i++)
                #pragma unroll
                for (int j = 0; j < 4; j++) acc[i][j] += a[i] * b[j];
        }
        // stage next tile into the alternate buffer (safe: last read of that
        // buffer completed before the sync that ended iteration t-1)
        if (t + 1 < NT) {
            const int nxt = (t + 1) & 1;
            #pragma unroll
            for (int rr = 0; rr < AR; rr++) {
                int r = ar + rr * 64;
                As[nxt][ac + 0][r] = aReg[rr].x; As[nxt][ac + 1][r] = aReg[rr].y;
                As[nxt][ac + 2][r] = aReg[rr].z; As[nxt][ac + 3][r] = aReg[rr].w;
            }
            *(float4*)&Bs[nxt][br][bcl] = bReg;
            __syncthreads();
        }
    }
}

// ---------------- plain GEMM: C = act(A@B + bias). ACT: 0=none,1=gelu,2=*8 ----------------
template <int K, int NC, int ACT, bool HAS_BIAS, int TM>
__global__ void __launch_bounds__(256) gemm_kernel(const float* __restrict__ A,
                                                   const float* __restrict__ B,
                                                   const float* __restrict__ bias,
                                                   float* __restrict__ C, int M) {
    constexpr int RM = TM / 16;
    const int bm = blockIdx.y * TM, bn = blockIdx.x * 64;
    const int tx = threadIdx.x & 15, ty = threadIdx.x >> 4;
    float acc[RM][4];
    gemm_core<K, TM>(A, B, NC, bm, bn, M, acc);

    float4 bi = make_float4(0.f, 0.f, 0.f, 0.f);
    if (HAS_BIAS) bi = *(const float4*)(bias + bn + tx * 4);
    #pragma unroll
    for (int i = 0; i < RM; i++) {
        int row = bm + ty * RM + i;
        if (row >= M) continue;
        float4 out;
        float* o = &out.x;
        const float* bb = &bi.x;
        #pragma unroll
        for (int j = 0; j < 4; j++) {
            float v = acc[i][j];
            if (HAS_BIAS) v += bb[j];
            if (ACT == 1) v = 0.5f * v * (1.f + erff(v * 0.70710678118654752f));
            else if (ACT == 2) v *= 8.0f;
            o[j] = v;
        }
        *(float4*)(C + (size_t)row * NC + bn + tx * 4) = out;
    }
}

// ---------------- xh GEMM + attention-score epilogue ----------------
// NC=HC=256, blockIdx.x = head (N-tile == one head). Writes C and g_as/g_ad.
__global__ void __launch_bounds__(256) gemm_att_kernel(const float* __restrict__ A,
                                                       const float* __restrict__ B,
                                                       float* __restrict__ C,
                                                       const float* __restrict__ att_s,
                                                       const float* __restrict__ att_d,
                                                       int M) {
    const int h = blockIdx.x;
    const int bm = blockIdx.y * 128, bn = h * 64;
    const int tx = threadIdx.x & 15, ty = threadIdx.x >> 4;
    float acc[8][4];
    gemm_core<HID, 128>(A, B, HC, bm, bn, M, acc);

    float4 ws = *(const float4*)(att_s + h * CHD + tx * 4);
    float4 wd = *(const float4*)(att_d + h * CHD + tx * 4);
    #pragma unroll
    for (int i = 0; i < 8; i++) {
        int row = bm + ty * 8 + i;
        float s1 = acc[i][0] * ws.x + acc[i][1] * ws.y + acc[i][2] * ws.z + acc[i][3] * ws.w;
        float s2 = acc[i][0] * wd.x + acc[i][1] * wd.y + acc[i][2] * wd.z + acc[i][3] * wd.w;
        #pragma unroll
        for (int off = 8; off; off >>= 1) {
            s1 += __shfl_xor_sync(0xffffffffu, s1, off, 16);
            s2 += __shfl_xor_sync(0xffffffffu, s2, off, 16);
        }
        if (row < M) {
            *(float4*)(C + (size_t)row * HC + bn + tx * 4) =
                make_float4(acc[i][0], acc[i][1], acc[i][2], acc[i][3]);
            if (tx == 0) { g_as[row * NH + h] = s1; g_ad[row * NH + h] = s2; }
        }
    }
}

// ---------------- W2 GEMM + bias + LayerNorm + residual epilogue ----------------
// NC=HID=64 (single N-tile covers full row). dst = h + LN(A@B + b2).
// dst is g_h for inner layers, d_out for the last layer (g_h is dead after).
__global__ void __launch_bounds__(256) gemm_ln_kernel(const float* __restrict__ A,
                                                      const float* __restrict__ B,
                                                      const float* __restrict__ bias,
                                                      const float* __restrict__ lng,
                                                      const float* __restrict__ lnb,
                                                      float* __restrict__ dst,
                                                      int M) {
    const int bm = blockIdx.y * 64;
    const int tx = threadIdx.x & 15, ty = threadIdx.x >> 4;
    float acc[4][4];
    gemm_core<DFF, 64>(A, B, HID, bm, 0, M, acc);

    float4 bi = *(const float4*)(bias + tx * 4);
    float4 gv = *(const float4*)(lng + tx * 4);
    float4 bv = *(const float4*)(lnb + tx * 4);
    const float* bip = &bi.x;
    const float* gp = &gv.x;
    const float* bp = &bv.x;

    #pragma unroll
    for (int i = 0; i < 4; i++) {
        int row = bm + ty * 4 + i;
        float v[4];
        float S = 0.f, Q = 0.f;
        #pragma unroll
        for (int j = 0; j < 4; j++) {
            v[j] = acc[i][j] + bip[j];
            S += v[j];
            Q += v[j] * v[j];
        }
        #pragma unroll
        for (int off = 8; off; off >>= 1) {
            S += __shfl_xor_sync(0xffffffffu, S, off, 16);
            Q += __shfl_xor_sync(0xffffffffu, Q, off, 16);
        }
        float mean = S * (1.f / HID);
        float var = Q * (1.f / HID) - mean * mean;
        float rstd = rsqrtf(var + 1e-5f);
        if (row < M) {
            float4 hold = *(const float4*)(g_h + (size_t)row * HID + tx * 4);
            float* hp = &hold.x;
            float4 hnew;
            float* np = &hnew.x;
            #pragma unroll
            for (int j = 0; j < 4; j++)
                np[j] = hp[j] + (v[j] - mean) * rstd * gp[j] + bp[j];
            *(float4*)(dst + (size_t)row * HID + tx * 4) = hnew;
        }
    }
}

// ---------------- aggregation: warp per destination node ----------------
__global__ void __launch_bounds__(256) agg_kernel(const float* __restrict__ bc_l) {
    int gid = blockIdx.x * blockDim.x + threadIdx.x;
    int i = gid >> 5;
    if (i >= NN) return;
    int lane = gid & 31;
    int beg = g_rowptr[i], end = g_rowptr[i + 1];

    float4 asi = *(const float4*)&g_as[i * 4];
    float4 adi = *(const float4*)&g_ad[i * 4];

    // pass 1: segment max per head (self-loop seeds the max)
    float m0 = lrelu(asi.x + adi.x);
    float m1 = lrelu(asi.y + adi.y);
    float m2 = lrelu(asi.z + adi.z);
    float m3 = lrelu(asi.w + adi.w);
    for (int j = beg + lane; j < end; j += 32) {
        int s = g_col[j];
        float4 as = *(const float4*)&g_as[s * 4];
        m0 = fmaxf(m0, lrelu(as.x + adi.x));
        m1 = fmaxf(m1, lrelu(as.y + adi.y));
        m2 = fmaxf(m2, lrelu(as.z + adi.z));
        m3 = fmaxf(m3, lrelu(as.w + adi.w));
    }
    #pragma unroll
    for (int off = 16; off; off >>= 1) {
        m0 = fmaxf(m0, __shfl_xor_sync(0xffffffffu, m0, off));
        m1 = fmaxf(m1, __shfl_xor_sync(0xffffffffu, m1, off));
        m2 = fmaxf(m2, __shfl_xor_sync(0xffffffffu, m2, off));
        m3 = fmaxf(m3, __shfl_xor_sync(0xffffffffu, m3, off));
    }

    int myh = lane >> 3;  // lane covers channels [lane*8, lane*8+8) -> head lane/8
    float mh  = (myh == 0) ? m0 : (myh == 1) ? m1 : (myh == 2) ? m2 : m3;
    float adh = (myh == 0) ? adi.x : (myh == 1) ? adi.y : (myh == 2) ? adi.z : adi.w;
    float ash_self = (myh == 0) ? asi.x : (myh == 1) ? asi.y : (myh == 2) ? asi.z : asi.w;

    float acc[8] = {0, 0, 0, 0, 0, 0, 0, 0};
    float z = 0.f;

    // self-loop message
    {
        float wgt = expf(lrelu(ash_self + adh) - mh);
        z += wgt;
        const float4* row = (const float4*)&g_xh[(size_t)i * HC];
        float4 v1 = row[lane * 2], v2 = row[lane * 2 + 1];
        acc[0] += wgt * v1.x; acc[1] += wgt * v1.y; acc[2] += wgt * v1.z; acc[3] += wgt * v1.w;
        acc[4] += wgt * v2.x; acc[5] += wgt * v2.y; acc[6] += wgt * v2.z; acc[7] += wgt * v2.w;
    }

    // pass 2: unrolled x4 over incoming edges — issue all four rows' loads
    // before consuming any (MLP=4 on the dependent gather chain).
    int j = beg;
    for (; j + 3 < end; j += 4) {
        int s0 = g_col[j], s1 = g_col[j + 1], s2 = g_col[j + 2], s3 = g_col[j + 3];
        float e0 = g_as[s0 * 4 + myh];
        float e1 = g_as[s1 * 4 + myh];
        float e2 = g_as[s2 * 4 + myh];
        float e3 = g_as[s3 * 4 + myh];
        const float4* r0 = (const float4*)&g_xh[(size_t)s0 * HC];
        const float4* r1 = (const float4*)&g_xh[(size_t)s1 * HC];
        const float4* r2 = (const float4*)&g_xh[(size_t)s2 * HC];
        const float4* r3 = (const float4*)&g_xh[(size_t)s3 * HC];
        float4 a1 = r0[lane * 2], a2 = r0[lane * 2 + 1];
        float4 b1 = r1[lane * 2], b2 = r1[lane * 2 + 1];
        float4 c1 = r2[lane * 2], c2 = r2[lane * 2 + 1];
        float4 d1 = r3[lane * 2], d2 = r3[lane * 2 + 1];
        float w0 = expf(lrelu(e0 + adh) - mh);
        float w1 = expf(lrelu(e1 + adh) - mh);
        float w2 = expf(lrelu(e2 + adh) - mh);
        float w3 = expf(lrelu(e3 + adh) - mh);
        z += (w0 + w1) + (w2 + w3);
        acc[0] += w0 * a1.x + w1 * b1.x + w2 * c1.x + w3 * d1.x;
        acc[1] += w0 * a1.y + w1 * b1.y + w2 * c1.y + w3 * d1.y;
        acc[2] += w0 * a1.z + w1 * b1.z + w2 * c1.z + w3 * d1.z;
        acc[3] += w0 * a1.w + w1 * b1.w + w2 * c1.w + w3 * d1.w;
        acc[4] += w0 * a2.x + w1 * b2.x + w2 * c2.x + w3 * d2.x;
        acc[5] += w0 * a2.y + w1 * b2.y + w2 * c2.y + w3 * d2.y;
        acc[6] += w0 * a2.z + w1 * b2.z + w2 * c2.z + w3 * d2.z;
        acc[7] += w0 * a2.w + w1 * b2.w + w2 * c2.w + w3 * d2.w;
    }
    for (; j < end; j++) {
        int s = g_col[j];
        float wgt = expf(lrelu(g_as[s * 4 + myh] + adh) - mh);
        z += wgt;
        const float4* row = (const float4*)&g_xh[(size_t)s * HC];
        float4 v1 = row[lane * 2], v2 = row[lane * 2 + 1];
        acc[0] += wgt * v1.x; acc[1] += wgt * v1.y; acc[2] += wgt * v1.z; acc[3] += wgt * v1.w;
        acc[4] += wgt * v2.x; acc[5] += wgt * v2.y; acc[6] += wgt * v2.z; acc[7] += wgt * v2.w;
    }

    float inv = 1.f / (z + 1e-16f);
    int base = lane * 8;
    float4 o1 = make_float4(acc[0] * inv + bc_l[base + 0], acc[1] * inv + bc_l[base + 1],
                            acc[2] * inv + bc_l[base + 2], acc[3] * inv + bc_l[base + 3]);
    float4 o2 = make_float4(acc[4] * inv + bc_l[base + 4], acc[5] * inv + bc_l[base + 5],
                            acc[6] * inv + bc_l[base + 6], acc[7] * inv + bc_l[base + 7]);
    *(float4*)&g_agg[(size_t)i * HC + base]     = o1;
    *(float4*)&g_agg[(size_t)i * HC + base + 4] = o2;
}

// ---------------- launch ----------------
extern "C" void kernel_launch(void* const* d_in, const int* in_sizes, int n_in,
                              void* d_out, int out_size) {
    const float* x     = (const float*)d_in[0];
    const int*   ei    = (const int*)d_in[1];
    const float* We    = (const float*)d_in[2];
    const float* be    = (const float*)d_in[3];
    const float* Wc    = (const float*)d_in[4];
    const float* att_s = (const float*)d_in[5];
    const float* att_d = (const float*)d_in[6];
    const float* bc    = (const float*)d_in[7];
    const float* W1    = (const float*)d_in[8];
    const float* b1    = (const float*)d_in[9];
    const float* W2    = (const float*)d_in[10];
    const float* b2    = (const float*)d_in[11];
    const float* lng   = (const float*)d_in[12];
    const float* lnb   = (const float*)d_in[13];
    float* out = (float*)d_out;

    void *ph, *pxh, *pagg, *pf1;
    cudaGetSymbolAddress(&ph,  g_h);
    cudaGetSymbolAddress(&pxh, g_xh);
    cudaGetSymbolAddress(&pagg, g_agg);
    cudaGetSymbolAddress(&pf1, g_f1);
    float* hbuf  = (float*)ph;
    float* xhbuf = (float*)pxh;
    float* aggbuf = (float*)pagg;
    float* f1buf = (float*)pf1;

    const int MB128 = (NN + 127) / 128;  // 157
    const int MB64  = (NN + 63) / 64;    // 313

    // CSR build (per-launch; edge_index is an input)
    zero_kernel<<<(NN + 255) / 256, 256>>>();
    count_kernel<<<(EE + 255) / 256, 256>>>(ei);
    scan_kernel<<<1, 1024>>>();
    scatter_kernel<<<(EE + 255) / 256, 256>>>(ei);

    // embed: h = (x @ We + be) * 8   (64-row tile: 313 CTAs, better wave balance)
    gemm_kernel<INDIM, HID, 2, true, 64><<<dim3(1, MB64), 256>>>(x, We, be, hbuf, NN);

    for (int l = 0; l < NL; l++) {
        // xh = h @ Wc[l]  (+ fused attention scores)
        gemm_att_kernel<<<dim3(NH, MB128), 256>>>(
            hbuf, Wc + (size_t)l * HID * HC, xhbuf,
            att_s + (size_t)l * NH * CHD, att_d + (size_t)l * NH * CHD, NN);
        // softmax-weighted aggregation (+ bc)
        agg_kernel<<<(NN * 32 + 255) / 256, 256>>>(bc + (size_t)l * HC);
        // FFN up + gelu
        gemm_kernel<HC, DFF, 1, true, 128><<<dim3(DFF / 64, MB128), 256>>>(
            aggbuf, W1 + (size_t)l * HC * DFF, b1 + (size_t)l * DFF, f1buf, NN);
        // FFN down + bias + LN + residual (last layer writes d_out directly)
        gemm_ln_kernel<<<dim3(1, MB64), 256>>>(
            f1buf, W2 + (size_t)l * DFF * HID, b2 + (size_t)l * HID,
            lng + (size_t)l * HID, lnb + (size_t)l * HID,
            (l == NL - 1) ? out : hbuf, NN);
    }
}

// round 15
// speedup vs baseline: 1.0667x; 1.0667x over previous
#include <cuda_runtime.h>
#include <math.h>

#define NN   20000
#define EE   320000
#define INDIM 256
#define HID  64
#define NH   4
#define CHD  64
#define HC   256   // NH*CHD
#define DFF  128
#define NL   4

// ---------------- scratch (device globals; no allocation allowed) ----------------
__device__ float g_h  [(size_t)NN * HID];   // hidden state
__device__ float g_xh [(size_t)NN * HC];    // per-layer projected features
__device__ float g_agg[(size_t)NN * HC];    // aggregated messages
__device__ float g_f1 [(size_t)NN * DFF];   // FFN intermediate
__device__ float g_as [(size_t)NN * NH];    // attention scores (src side)
__device__ float g_ad [(size_t)NN * NH];    // attention scores (dst side)
__device__ int   g_deg[NN];
__device__ int   g_fill[NN];
__device__ int   g_rowptr[NN + 1];
__device__ int   g_col[EE];

__device__ __forceinline__ float lrelu(float x) { return x > 0.f ? x : 0.2f * x; }

// ---- packed f32x2 helpers (FFMA2: one issue slot, two fp32 FMAs) ----
__device__ __forceinline__ unsigned long long pack2(float x, float y) {
    unsigned long long r;
    asm("mov.b64 %0, {%1, %2};" : "=l"(r) : "f"(x), "f"(y));
    return r;
}
__device__ __forceinline__ void fma2(unsigned long long& d,
                                     unsigned long long a, unsigned long long b) {
    asm("fma.rn.f32x2 %0, %1, %2, %0;" : "+l"(d) : "l"(a), "l"(b));
}
__device__ __forceinline__ void unpack2(unsigned long long p, float& x, float& y) {
    asm("mov.b64 {%0, %1}, %2;" : "=f"(x), "=f"(y) : "l"(p));
}

// ---------------- CSR build ----------------
__global__ void zero_kernel() {
    int i = blockIdx.x * blockDim.x + threadIdx.x;
    if (i < NN) { g_deg[i] = 0; g_fill[i] = 0; }
}

__global__ void count_kernel(const int* __restrict__ ei) {
    int e = blockIdx.x * blockDim.x + threadIdx.x;
    if (e < EE) atomicAdd(&g_deg[ei[EE + e]], 1);
}

__global__ void scan_kernel() {
    __shared__ int s[1024];
    int t = threadIdx.x;
    const int CHK = (NN + 1023) / 1024;  // 20
    int base = t * CHK;
    int sum = 0;
    #pragma unroll
    for (int i = 0; i < CHK; i++) {
        int idx = base + i;
        if (idx < NN) sum += g_deg[idx];
    }
    s[t] = sum;
    __syncthreads();
    for (int off = 1; off < 1024; off <<= 1) {
        int v = (t >= off) ? s[t - off] : 0;
        __syncthreads();
        s[t] += v;
        __syncthreads();
    }
    int run = (t == 0) ? 0 : s[t - 1];
    #pragma unroll
    for (int i = 0; i < CHK; i++) {
        int idx = base + i;
        if (idx < NN) { g_rowptr[idx] = run; run += g_deg[idx]; }
    }
    if (t == 0) g_rowptr[NN] = s[1023];
}

__global__ void scatter_kernel(const int* __restrict__ ei) {
    int e = blockIdx.x * blockDim.x + threadIdx.x;
    if (e < EE) {
        int d = ei[EE + e];
        int pos = g_rowptr[d] + atomicAdd(&g_fill[d], 1);
        g_col[pos] = ei[e];  // src
    }
}

// ======================= GEMM core (double-buffered + FFMA2) ======================
// TM x 64 block tile (TM = 128 or 64), 256 threads, (TM/16) x 4 per thread, k-tile 16.
// Inner loop uses fma.rn.f32x2: accumulators paired along rows so A pairs come free
// from the float4 smem loads; only the 4 {b,b} packs per k are extra (alu pipe).
// acc layout: thread (tx = tid&15, ty = tid>>4) owns rows bm+ty*RM..+RM-1, cols bn+tx*4..+3
template <int K, int TM>
__device__ __forceinline__ void gemm_core(const float* __restrict__ A,
                                          const float* __restrict__ B, int NC,
                                          int bm, int bn, int M,
                                          float acc[TM / 16][4]) {
    constexpr int RM = TM / 16;
    constexpr int RMP = RM / 2;       // row pairs
    constexpr int NT = K / 16;        // number of k-tiles
    constexpr int AR = TM / 64;       // A float4 loads per thread per tile
    __shared__ __align__(16) float As[2][16][TM + 8];  // transposed: As[buf][k][m]
    __shared__ __align__(16) float Bs[2][16][68];      // Bs[buf][k][n]
    const int tid = threadIdx.x;
    const int tx = tid & 15, ty = tid >> 4;

    unsigned long long accp[RMP][4];
    #pragma unroll
    for (int i = 0; i < RMP; i++)
        #pragma unroll
        for (int j = 0; j < 4; j++) accp[i][j] = 0ull;  // bit pattern = {0.f, 0.f}

    const int ar = tid >> 2;          // 0..63
    const int ac = (tid & 3) * 4;     // 0,4,8,12
    const int br = tid >> 4;          // 0..15
    const int bcl = (tid & 15) * 4;   // 0..60

    float4 aReg[AR];
    float4 bReg;

    // prologue: load tile 0 into buffer 0
    #pragma unroll
    for (int rr = 0; rr < AR; rr++) {
        int row = bm + ar + rr * 64;
        aReg[rr] = make_float4(0.f, 0.f, 0.f, 0.f);
        if (row < M) aReg[rr] = *(const float4*)(A + (size_t)row * K + ac);
    }
    bReg = *(const float4*)(B + (size_t)br * NC + bn + bcl);
    #pragma unroll
    for (int rr = 0; rr < AR; rr++) {
        int r = ar + rr * 64;
        As[0][ac + 0][r] = aReg[rr].x; As[0][ac + 1][r] = aReg[rr].y;
        As[0][ac + 2][r] = aReg[rr].z; As[0][ac + 3][r] = aReg[rr].w;
    }
    *(float4*)&Bs[0][br][bcl] = bReg;
    __syncthreads();

    #pragma unroll
    for (int t = 0; t < NT; t++) {
        const int cur = t & 1;
        // issue next tile's global loads before compute (latency hidden by FMAs)
        if (t + 1 < NT) {
            int k0 = (t + 1) * 16;
            #pragma unroll
            for (int rr = 0; rr < AR; rr++) {
                int row = bm + ar + rr * 64;
                aReg[rr] = make_float4(0.f, 0.f, 0.f, 0.f);
                if (row < M) aReg[rr] = *(const float4*)(A + (size_t)row * K + k0 + ac);
            }
            bReg = *(const float4*)(B + (size_t)(k0 + br) * NC + bn + bcl);
        }
        // compute on current buffer
        #pragma unroll
        for (int k = 0; k < 16; k++) {
            unsigned long long a2[RMP];
            #pragma unroll
            for (int p = 0; p < RMP / 2; p++) {
                ulonglong2 v = *(const ulonglong2*)&As[cur][k][ty * RM + p * 4];
                a2[2 * p] = v.x; a2[2 * p + 1] = v.y;
            }
            float4 bv = *(const float4*)&Bs[cur][k][tx * 4];
            unsigned long long bb[4];
            bb[0] = pack2(bv.x, bv.x);
            bb[1] = pack2(bv.y, bv.y);
            bb[2] = pack2(bv.z, bv.z);
            bb[3] = pack2(bv.w, bv.w);
            #pragma unroll
            for (int ip = 0; ip < RMP; ip++)
                #pragma unroll
                for (int j = 0; j < 4; j++) fma2(accp[ip][j], a2[ip], bb[j]);
        }
        // stage next tile into the alternate buffer (safe: last read of that
        // buffer completed before the sync that ended iteration t-1)
        if (t + 1 < NT) {
            const int nxt = (t + 1) & 1;
            #pragma unroll
            for (int rr = 0; rr < AR; rr++) {
                int r = ar + rr * 64;
                As[nxt][ac + 0][r] = aReg[rr].x; As[nxt][ac + 1][r] = aReg[rr].y;
                As[nxt][ac + 2][r] = aReg[rr].z; As[nxt][ac + 3][r] = aReg[rr].w;
            }
            *(float4*)&Bs[nxt][br][bcl] = bReg;
            __syncthreads();
        }
    }

    // unpack row pairs into the scalar acc layout used by the epilogues
    #pragma unroll
    for (int ip = 0; ip < RMP; ip++)
        #pragma unroll
        for (int j = 0; j < 4; j++)
            unpack2(accp[ip][j], acc[2 * ip][j], acc[2 * ip + 1][j]);
}

// ---------------- plain GEMM: C = act(A@B + bias). ACT: 0=none,1=gelu,2=*8 ----------------
template <int K, int NC, int ACT, bool HAS_BIAS, int TM>
__global__ void __launch_bounds__(256) gemm_kernel(const float* __restrict__ A,
                                                   const float* __restrict__ B,
                                                   const float* __restrict__ bias,
                                                   float* __restrict__ C, int M) {
    constexpr int RM = TM / 16;
    const int bm = blockIdx.y * TM, bn = blockIdx.x * 64;
    const int tx = threadIdx.x & 15, ty = threadIdx.x >> 4;
    float acc[RM][4];
    gemm_core<K, TM>(A, B, NC, bm, bn, M, acc);

    float4 bi = make_float4(0.f, 0.f, 0.f, 0.f);
    if (HAS_BIAS) bi = *(const float4*)(bias + bn + tx * 4);
    #pragma unroll
    for (int i = 0; i < RM; i++) {
        int row = bm + ty * RM + i;
        if (row >= M) continue;
        float4 out;
        float* o = &out.x;
        const float* bb = &bi.x;
        #pragma unroll
        for (int j = 0; j < 4; j++) {
            float v = acc[i][j];
            if (HAS_BIAS) v += bb[j];
            if (ACT == 1) v = 0.5f * v * (1.f + erff(v * 0.70710678118654752f));
            else if (ACT == 2) v *= 8.0f;
            o[j] = v;
        }
        *(float4*)(C + (size_t)row * NC + bn + tx * 4) = out;
    }
}

// ---------------- xh GEMM + attention-score epilogue ----------------
// NC=HC=256, blockIdx.x = head (N-tile == one head). Writes C and g_as/g_ad.
__global__ void __launch_bounds__(256) gemm_att_kernel(const float* __restrict__ A,
                                                       const float* __restrict__ B,
                                                       float* __restrict__ C,
                                                       const float* __restrict__ att_s,
                                                       const float* __restrict__ att_d,
                                                       int M) {
    const int h = blockIdx.x;
    const int bm = blockIdx.y * 128, bn = h * 64;
    const int tx = threadIdx.x & 15, ty = threadIdx.x >> 4;
    float acc[8][4];
    gemm_core<HID, 128>(A, B, HC, bm, bn, M, acc);

    float4 ws = *(const float4*)(att_s + h * CHD + tx * 4);
    float4 wd = *(const float4*)(att_d + h * CHD + tx * 4);
    #pragma unroll
    for (int i = 0; i < 8; i++) {
        int row = bm + ty * 8 + i;
        float s1 = acc[i][0] * ws.x + acc[i][1] * ws.y + acc[i][2] * ws.z + acc[i][3] * ws.w;
        float s2 = acc[i][0] * wd.x + acc[i][1] * wd.y + acc[i][2] * wd.z + acc[i][3] * wd.w;
        #pragma unroll
        for (int off = 8; off; off >>= 1) {
            s1 += __shfl_xor_sync(0xffffffffu, s1, off, 16);
            s2 += __shfl_xor_sync(0xffffffffu, s2, off, 16);
        }
        if (row < M) {
            *(float4*)(C + (size_t)row * HC + bn + tx * 4) =
                make_float4(acc[i][0], acc[i][1], acc[i][2], acc[i][3]);
            if (tx == 0) { g_as[row * NH + h] = s1; g_ad[row * NH + h] = s2; }
        }
    }
}

// ---------------- W2 GEMM + bias + LayerNorm + residual epilogue ----------------
// NC=HID=64 (single N-tile covers full row). dst = h + LN(A@B + b2).
// dst is g_h for inner layers, d_out for the last layer (g_h is dead after).
__global__ void __launch_bounds__(256) gemm_ln_kernel(const float* __restrict__ A,
                                                      const float* __restrict__ B,
                                                      const float* __restrict__ bias,
                                                      const float* __restrict__ lng,
                                                      const float* __restrict__ lnb,
                                                      float* __restrict__ dst,
                                                      int M) {
    const int bm = blockIdx.y * 64;
    const int tx = threadIdx.x & 15, ty = threadIdx.x >> 4;
    float acc[4][4];
    gemm_core<DFF, 64>(A, B, HID, bm, 0, M, acc);

    float4 bi = *(const float4*)(bias + tx * 4);
    float4 gv = *(const float4*)(lng + tx * 4);
    float4 bv = *(const float4*)(lnb + tx * 4);
    const float* bip = &bi.x;
    const float* gp = &gv.x;
    const float* bp = &bv.x;

    #pragma unroll
    for (int i = 0; i < 4; i++) {
        int row = bm + ty * 4 + i;
        float v[4];
        float S = 0.f, Q = 0.f;
        #pragma unroll
        for (int j = 0; j < 4; j++) {
            v[j] = acc[i][j] + bip[j];
            S += v[j];
            Q += v[j] * v[j];
        }
        #pragma unroll
        for (int off = 8; off; off >>= 1) {
            S += __shfl_xor_sync(0xffffffffu, S, off, 16);
            Q += __shfl_xor_sync(0xffffffffu, Q, off, 16);
        }
        float mean = S * (1.f / HID);
        float var = Q * (1.f / HID) - mean * mean;
        float rstd = rsqrtf(var + 1e-5f);
        if (row < M) {
            float4 hold = *(const float4*)(g_h + (size_t)row * HID + tx * 4);
            float* hp = &hold.x;
            float4 hnew;
            float* np = &hnew.x;
            #pragma unroll
            for (int j = 0; j < 4; j++)
                np[j] = hp[j] + (v[j] - mean) * rstd * gp[j] + bp[j];
            *(float4*)(dst + (size_t)row * HID + tx * 4) = hnew;
        }
    }
}

// ---------------- aggregation: warp per destination node ----------------
__global__ void __launch_bounds__(256) agg_kernel(const float* __restrict__ bc_l) {
    int gid = blockIdx.x * blockDim.x + threadIdx.x;
    int i = gid >> 5;
    if (i >= NN) return;
    int lane = gid & 31;
    int beg = g_rowptr[i], end = g_rowptr[i + 1];

    float4 asi = *(const float4*)&g_as[i * 4];
    float4 adi = *(const float4*)&g_ad[i * 4];

    // pass 1: segment max per head (self-loop seeds the max)
    float m0 = lrelu(asi.x + adi.x);
    float m1 = lrelu(asi.y + adi.y);
    float m2 = lrelu(asi.z + adi.z);
    float m3 = lrelu(asi.w + adi.w);
    for (int j = beg + lane; j < end; j += 32) {
        int s = g_col[j];
        float4 as = *(const float4*)&g_as[s * 4];
        m0 = fmaxf(m0, lrelu(as.x + adi.x));
        m1 = fmaxf(m1, lrelu(as.y + adi.y));
        m2 = fmaxf(m2, lrelu(as.z + adi.z));
        m3 = fmaxf(m3, lrelu(as.w + adi.w));
    }
    #pragma unroll
    for (int off = 16; off; off >>= 1) {
        m0 = fmaxf(m0, __shfl_xor_sync(0xffffffffu, m0, off));
        m1 = fmaxf(m1, __shfl_xor_sync(0xffffffffu, m1, off));
        m2 = fmaxf(m2, __shfl_xor_sync(0xffffffffu, m2, off));
        m3 = fmaxf(m3, __shfl_xor_sync(0xffffffffu, m3, off));
    }

    int myh = lane >> 3;  // lane covers channels [lane*8, lane*8+8) -> head lane/8
    float mh  = (myh == 0) ? m0 : (myh == 1) ? m1 : (myh == 2) ? m2 : m3;
    float adh = (myh == 0) ? adi.x : (myh == 1) ? adi.y : (myh == 2) ? adi.z : adi.w;
    float ash_self = (myh == 0) ? asi.x : (myh == 1) ? asi.y : (myh == 2) ? asi.z : asi.w;

    float acc[8] = {0, 0, 0, 0, 0, 0, 0, 0};
    float z = 0.f;

    // self-loop message
    {
        float wgt = expf(lrelu(ash_self + adh) - mh);
        z += wgt;
        const float4* row = (const float4*)&g_xh[(size_t)i * HC];
        float4 v1 = row[lane * 2], v2 = row[lane * 2 + 1];
        acc[0] += wgt * v1.x; acc[1] += wgt * v1.y; acc[2] += wgt * v1.z; acc[3] += wgt * v1.w;
        acc[4] += wgt * v2.x; acc[5] += wgt * v2.y; acc[6] += wgt * v2.z; acc[7] += wgt * v2.w;
    }

    // pass 2: unrolled x4 over incoming edges — issue all four rows' loads
    // before consuming any (MLP=4 on the dependent gather chain).
    int j = beg;
    for (; j + 3 < end; j += 4) {
        int s0 = g_col[j], s1 = g_col[j + 1], s2 = g_col[j + 2], s3 = g_col[j + 3];
        float e0 = g_as[s0 * 4 + myh];
        float e1 = g_as[s1 * 4 + myh];
        float e2 = g_as[s2 * 4 + myh];
        float e3 = g_as[s3 * 4 + myh];
        const float4* r0 = (const float4*)&g_xh[(size_t)s0 * HC];
        const float4* r1 = (const float4*)&g_xh[(size_t)s1 * HC];
        const float4* r2 = (const float4*)&g_xh[(size_t)s2 * HC];
        const float4* r3 = (const float4*)&g_xh[(size_t)s3 * HC];
        float4 a1 = r0[lane * 2], a2 = r0[lane * 2 + 1];
        float4 b1 = r1[lane * 2], b2 = r1[lane * 2 + 1];
        float4 c1 = r2[lane * 2], c2 = r2[lane * 2 + 1];
        float4 d1 = r3[lane * 2], d2 = r3[lane * 2 + 1];
        float w0 = expf(lrelu(e0 + adh) - mh);
        float w1 = expf(lrelu(e1 + adh) - mh);
        float w2 = expf(lrelu(e2 + adh) - mh);
        float w3 = expf(lrelu(e3 + adh) - mh);
        z += (w0 + w1) + (w2 + w3);
        acc[0] += w0 * a1.x + w1 * b1.x + w2 * c1.x + w3 * d1.x;
        acc[1] += w0 * a1.y + w1 * b1.y + w2 * c1.y + w3 * d1.y;
        acc[2] += w0 * a1.z + w1 * b1.z + w2 * c1.z + w3 * d1.z;
        acc[3] += w0 * a1.w + w1 * b1.w + w2 * c1.w + w3 * d1.w;
        acc[4] += w0 * a2.x + w1 * b2.x + w2 * c2.x + w3 * d2.x;
        acc[5] += w0 * a2.y + w1 * b2.y + w2 * c2.y + w3 * d2.y;
        acc[6] += w0 * a2.z + w1 * b2.z + w2 * c2.z + w3 * d2.z;
        acc[7] += w0 * a2.w + w1 * b2.w + w2 * c2.w + w3 * d2.w;
    }
    for (; j < end; j++) {
        int s = g_col[j];
        float wgt = expf(lrelu(g_as[s * 4 + myh] + adh) - mh);
        z += wgt;
        const float4* row = (const float4*)&g_xh[(size_t)s * HC];
        float4 v1 = row[lane * 2], v2 = row[lane * 2 + 1];
        acc[0] += wgt * v1.x; acc[1] += wgt * v1.y; acc[2] += wgt * v1.z; acc[3] += wgt * v1.w;
        acc[4] += wgt * v2.x; acc[5] += wgt * v2.y; acc[6] += wgt * v2.z; acc[7] += wgt * v2.w;
    }

    float inv = 1.f / (z + 1e-16f);
    int base = lane * 8;
    float4 o1 = make_float4(acc[0] * inv + bc_l[base + 0], acc[1] * inv + bc_l[base + 1],
                            acc[2] * inv + bc_l[base + 2], acc[3] * inv + bc_l[base + 3]);
    float4 o2 = make_float4(acc[4] * inv + bc_l[base + 4], acc[5] * inv + bc_l[base + 5],
                            acc[6] * inv + bc_l[base + 6], acc[7] * inv + bc_l[base + 7]);
    *(float4*)&g_agg[(size_t)i * HC + base]     = o1;
    *(float4*)&g_agg[(size_t)i * HC + base + 4] = o2;
}

// ---------------- launch ----------------
extern "C" void kernel_launch(void* const* d_in, const int* in_sizes, int n_in,
                              void* d_out, int out_size) {
    const float* x     = (const float*)d_in[0];
    const int*   ei    = (const int*)d_in[1];
    const float* We    = (const float*)d_in[2];
    const float* be    = (const float*)d_in[3];
    const float* Wc    = (const float*)d_in[4];
    const float* att_s = (const float*)d_in[5];
    const float* att_d = (const float*)d_in[6];
    const float* bc    = (const float*)d_in[7];
    const float* W1    = (const float*)d_in[8];
    const float* b1    = (const float*)d_in[9];
    const float* W2    = (const float*)d_in[10];
    const float* b2    = (const float*)d_in[11];
    const float* lng   = (const float*)d_in[12];
    const float* lnb   = (const float*)d_in[13];
    float* out = (float*)d_out;

    void *ph, *pxh, *pagg, *pf1;
    cudaGetSymbolAddress(&ph,  g_h);
    cudaGetSymbolAddress(&pxh, g_xh);
    cudaGetSymbolAddress(&pagg, g_agg);
    cudaGetSymbolAddress(&pf1, g_f1);
    float* hbuf  = (float*)ph;
    float* xhbuf = (float*)pxh;
    float* aggbuf = (float*)pagg;
    float* f1buf = (float*)pf1;

    const int MB128 = (NN + 127) / 128;  // 157
    const int MB64  = (NN + 63) / 64;    // 313

    // CSR build (per-launch; edge_index is an input)
    zero_kernel<<<(NN + 255) / 256, 256>>>();
    count_kernel<<<(EE + 255) / 256, 256>>>(ei);
    scan_kernel<<<1, 1024>>>();
    scatter_kernel<<<(EE + 255) / 256, 256>>>(ei);

    // embed: h = (x @ We + be) * 8   (64-row tile: 313 CTAs, better wave balance)
    gemm_kernel<INDIM, HID, 2, true, 64><<<dim3(1, MB64), 256>>>(x, We, be, hbuf, NN);

    for (int l = 0; l < NL; l++) {
        // xh = h @ Wc[l]  (+ fused attention scores)
        gemm_att_kernel<<<dim3(NH, MB128), 256>>>(
            hbuf, Wc + (size_t)l * HID * HC, xhbuf,
            att_s + (size_t)l * NH * CHD, att_d + (size_t)l * NH * CHD, NN);
        // softmax-weighted aggregation (+ bc)
        agg_kernel<<<(NN * 32 + 255) / 256, 256>>>(bc + (size_t)l * HC);
        // FFN up + gelu
        gemm_kernel<HC, DFF, 1, true, 128><<<dim3(DFF / 64, MB128), 256>>>(
            aggbuf, W1 + (size_t)l * HC * DFF, b1 + (size_t)l * DFF, f1buf, NN);
        // FFN down + bias + LN + residual (last layer writes d_out directly)
        gemm_ln_kernel<<<dim3(1, MB64), 256>>>(
            f1buf, W2 + (size_t)l * DFF * HID, b2 + (size_t)l * HID,
            lng + (size_t)l * HID, lnb + (size_t)l * HID,
            (l == NL - 1) ? out : hbuf, NN);
    }
}